// round 13
// baseline (speedup 1.0000x reference)
#include <cuda_runtime.h>
#include <math.h>

#define PI_F  3.14159265358979f
#define TWOPI 6.28318530717959f

typedef unsigned long long u64;

static __device__ __forceinline__ float clampf(float x, float lo, float hi) {
    return fminf(fmaxf(x, lo), hi);
}

// ---- packed f32x2 helpers (Blackwell FFMA2 path, PTX-only) ----
static __device__ __forceinline__ u64 pk2(float lo, float hi) {
    u64 r; asm("mov.b64 %0,{%1,%2};" : "=l"(r) : "f"(lo), "f"(hi)); return r;
}
static __device__ __forceinline__ void upk2(u64 v, float& lo, float& hi) {
    asm("mov.b64 {%0,%1},%2;" : "=f"(lo), "=f"(hi) : "l"(v));
}
static __device__ __forceinline__ u64 f2fma(u64 a, u64 b, u64 c) {
    u64 d; asm("fma.rn.f32x2 %0,%1,%2,%3;" : "=l"(d) : "l"(a), "l"(b), "l"(c)); return d;
}
static __device__ __forceinline__ u64 f2mul(u64 a, u64 b) {
    u64 d; asm("mul.rn.f32x2 %0,%1,%2;" : "=l"(d) : "l"(a), "l"(b)); return d;
}
static __device__ __forceinline__ u64 f2add(u64 a, u64 b) {
    u64 d; asm("add.rn.f32x2 %0,%1,%2;" : "=l"(d) : "l"(a), "l"(b)); return d;
}

// TWO rows per warp: lanes 0-15 -> row 2w, lanes 16-31 -> row 2w+1.
// Each lane owns 16 consecutive k (8 packed pairs), k0 = 16*(lane&15).
// k (and signs) pre-multiplied into z registers (f32x2: no spills at cap 51).
// Packed sin/cos pairs advance via the Chebyshev three-term recurrence
// w_{m+1} = (+-2cos2P)*w_m + w_{m-1}, eps=(+,+,-,-) folded into constants.
// T = tanh(u) tracked directly via the addition formula; the Moebius
// denominator 1/(1 - T*p) (|T*p| <= 0.1) is a 4-term Horner series
// (error <= 1.1e-5/step) - no MUFU.RCP on the state-update path.
__global__ void __launch_bounds__(128, 10) refiner_kernel(
    const float* __restrict__ z_real,
    const float* __restrict__ z_imag,
    const float* __restrict__ theta0_deg,
    const float* __restrict__ r0_m,
    const float* __restrict__ a_th_raw,
    const float* __restrict__ a_r_raw,
    const float* __restrict__ l_th_raw,
    const float* __restrict__ l_r_raw,
    float* __restrict__ out,
    int B)
{
    __shared__ float4 s_par[10];   // (a_th, a_r, l_th, l_r) per step
    int tid = threadIdx.x;
    if (tid < 10) {
        float4 p;
        p.x = clampf(log1pf(expf(a_th_raw[tid])), 1e-6f, 0.2f);
        p.y = clampf(log1pf(expf(a_r_raw[tid])),  1e-6f, 0.2f);
        p.z = clampf(log1pf(expf(l_th_raw[tid])), 1e-6f, 1.0f);
        p.w = clampf(log1pf(expf(l_r_raw[tid])),  1e-6f, 1.0f);
        s_par[tid] = p;
    }
    __syncthreads();

    int gwarp = (int)((blockIdx.x * blockDim.x + tid) >> 5);
    int lane  = tid & 31;
    int half  = lane >> 4;
    int hl    = lane & 15;
    int row   = gwarp * 2 + half;
    if (row >= B) return;

    const float k0f = (float)(hl * 16);

    // Load 16 z values per array; fold eps*k (and the zim minus) in.
    const float4* zr4 = reinterpret_cast<const float4*>(z_real + (size_t)row * 256) + hl * 4;
    const float4* zi4 = reinterpret_cast<const float4*>(z_imag + (size_t)row * 256) + hl * 4;
    u64 kzre[8], knzim[8];
    {
        float zr[16], zi[16];
        #pragma unroll
        for (int q4 = 0; q4 < 4; q4++) {
            float4 a = zr4[q4], b = zi4[q4];
            zr[q4*4+0]=a.x; zr[q4*4+1]=a.y; zr[q4*4+2]=a.z; zr[q4*4+3]=a.w;
            zi[q4*4+0]=b.x; zi[q4*4+1]=b.y; zi[q4*4+2]=b.z; zi[q4*4+3]=b.w;
        }
        #pragma unroll
        for (int j = 0; j < 8; j++) {
            float eps = ((j >> 1) & 1) ? -1.0f : 1.0f;   // +,+,-,-,+,+,-,-
            float ka = eps * (k0f + (float)(2*j));
            float kb = eps * (k0f + (float)(2*j) + 1.0f);
            kzre[j]  = pk2(ka * zr[2*j],  kb * zr[2*j+1]);
            knzim[j] = pk2(-ka * zi[2*j], -kb * zi[2*j+1]);
        }
    }

    const float EPS = 1e-6f;
    // direct tanh-space init: T = tanh(atanh(y)) = y (clipped)
    float T0 = clampf(theta0_deg[row] * (1.0f / 60.0f), -1.0f + EPS, 1.0f - EPS);
    float T1 = fmaf(2.0f, clampf(r0_m[row] * (1.0f / 2000.0f), EPS, 1.0f - EPS), -1.0f);

    const float C_GTH = (PI_F * PI_F / 3.0f) / 16.0f;
    const float C_GR  = -(0.4f * PI_F) / 16.0f;

    #pragma unroll 1
    for (int t = 0; t < 10; t++) {
        float4 par = s_par[t];   // a_th, a_r, l_th, l_r

        float th_rad = T0 * (60.0f * PI_F / 180.0f);
        float sth, cth;
        __sincosf(th_rad, &sth, &cth);
        float q = fmaf(-0.2f, T1 + 1.0f, 0.5f * sth);

        float Pr = TWOPI * (q - rintf(q));
        float sP, cP;
        __sincosf(Pr, &sP, &cP);
        float twocP  = cP + cP;
        float twoc2P = fmaf(twocP, twocP, -2.0f);     // 2*cos(2P)
        u64 aP = pk2(twoc2P, twoc2P);
        u64 aN = pk2(-twoc2P, -twoc2P);

        // step coefficients computed BEFORE v (off the critical path)
        float sech0 = fmaf(-T0, T0, 1.0f);
        float sech1 = fmaf(-T1, T1, 1.0f);
        float cg_th = C_GTH * cth * sech0;
        float cg_r  = C_GR * sech1;
        float acg_th = par.x * cg_th;
        float acg_r  = par.y * cg_r;

        // starting pairs: w0 = (s(a0), s(a0+P)), w1 = (s(a0+2P), s(a0+3P))
        float f = k0f * q;
        float a0 = TWOPI * (f - rintf(f));
        float s0_, c0_;
        __sincosf(a0, &s0_, &c0_);
        float s1_ = fmaf(s0_, cP, c0_ * sP);
        float c1_ = fmaf(c0_, cP, -(s0_ * sP));
        float s2_ = fmaf(twocP, s1_, -s0_);
        float c2_ = fmaf(twocP, c1_, -c0_);
        float s3_ = fmaf(twocP, s2_, -s1_);
        float c3_ = fmaf(twocP, c2_, -c1_);

        u64 psS = pk2(s0_, s1_), psC = pk2(c0_, c1_);   // w_0
        u64 cuS = pk2(s2_, s3_), cuC = pk2(c2_, c3_);   // w_1

        // m = 0, 1 (init accumulators with mul: no zero-pack)
        u64 accS = f2mul(kzre[0], psS);
        u64 accC = f2mul(knzim[0], psC);
        accS = f2fma(kzre[1], cuS, accS);
        accC = f2fma(knzim[1], cuC, accC);
        // m = 2..7: advance Chebyshev (alpha alternates -,+,-,+,-,+), accumulate
        #pragma unroll
        for (int m = 2; m < 8; m++) {
            u64 alpha = (m & 1) ? aP : aN;
            u64 nS = f2fma(alpha, cuS, psS);
            u64 nC = f2fma(alpha, cuC, psC);
            psS = cuS; cuS = nS;
            psC = cuC; cuC = nC;
            accS = f2fma(kzre[m], cuS, accS);
            accC = f2fma(knzim[m], cuC, accC);
        }

        u64 v2 = f2add(accS, accC);
        float vlo, vhi;
        upk2(v2, vlo, vhi);
        float v = vlo + vhi;
        #pragma unroll
        for (int o = 8; o > 0; o >>= 1)
            v += __shfl_xor_sync(0xffffffffu, v, o);

        float g_th = cg_th * v;
        float g_r  = cg_r * v;
        float den_th = fmaxf(fabsf(g_th), 1e-6f) + par.z;
        float den_r  = fmaxf(fabsf(g_r),  1e-6f) + par.w;
        float st_th = clampf(acg_th * v * __fdividef(1.0f, den_th), -0.1f, 0.1f);
        float st_r  = clampf(acg_r  * v * __fdividef(1.0f, den_r),  -0.1f, 0.1f);

        // T <- tanh(u - st); p = tanh(st) ~ st(1 - st^2/3).
        // 1/(1 - T*p) via 4-term Horner (|T*p| <= 0.1, err <= 1.1e-5): no RCP.
        float p_th = st_th * fmaf(st_th * st_th, -(1.0f / 3.0f), 1.0f);
        float p_r  = st_r  * fmaf(st_r  * st_r,  -(1.0f / 3.0f), 1.0f);
        float x0 = T0 * p_th;
        float x1 = T1 * p_r;
        float inv0 = fmaf(x0, fmaf(x0, fmaf(x0, fmaf(x0, 1.0f, 1.0f), 1.0f), 1.0f), 1.0f);
        float inv1 = fmaf(x1, fmaf(x1, fmaf(x1, fmaf(x1, 1.0f, 1.0f), 1.0f), 1.0f), 1.0f);
        T0 = (T0 - p_th) * inv0;
        T1 = (T1 - p_r)  * inv1;
    }

    if (hl == 0) {
        float2 o;
        o.x = 60.0f * T0;
        o.y = 1000.0f * (T1 + 1.0f);
        reinterpret_cast<float2*>(out)[row] = o;
    }
}

extern "C" void kernel_launch(void* const* d_in, const int* in_sizes, int n_in,
                              void* d_out, int out_size) {
    const float* z_real    = (const float*)d_in[0];
    const float* z_imag    = (const float*)d_in[1];
    const float* theta0    = (const float*)d_in[2];
    const float* r0        = (const float*)d_in[3];
    const float* a_th_raw  = (const float*)d_in[4];
    const float* a_r_raw   = (const float*)d_in[5];
    const float* l_th_raw  = (const float*)d_in[6];
    const float* l_r_raw   = (const float*)d_in[7];
    float* out = (float*)d_out;

    int B = in_sizes[2];
    int nwarps = (B + 1) / 2;
    int threads = 128;
    int blocks = (nwarps * 32 + threads - 1) / threads;
    refiner_kernel<<<blocks, threads>>>(z_real, z_imag, theta0, r0,
                                        a_th_raw, a_r_raw, l_th_raw, l_r_raw,
                                        out, B);
}

// round 14
// speedup vs baseline: 1.0010x; 1.0010x over previous
#include <cuda_runtime.h>
#include <math.h>

#define PI_F  3.14159265358979f
#define TWOPI 6.28318530717959f

typedef unsigned long long u64;

static __device__ __forceinline__ float clampf(float x, float lo, float hi) {
    return fminf(fmaxf(x, lo), hi);
}

// ---- packed f32x2 helpers (Blackwell FFMA2 path, PTX-only) ----
static __device__ __forceinline__ u64 pk2(float lo, float hi) {
    u64 r; asm("mov.b64 %0,{%1,%2};" : "=l"(r) : "f"(lo), "f"(hi)); return r;
}
static __device__ __forceinline__ void upk2(u64 v, float& lo, float& hi) {
    asm("mov.b64 {%0,%1},%2;" : "=f"(lo), "=f"(hi) : "l"(v));
}
static __device__ __forceinline__ u64 f2fma(u64 a, u64 b, u64 c) {
    u64 d; asm("fma.rn.f32x2 %0,%1,%2,%3;" : "=l"(d) : "l"(a), "l"(b), "l"(c)); return d;
}
static __device__ __forceinline__ u64 f2mul(u64 a, u64 b) {
    u64 d; asm("mul.rn.f32x2 %0,%1,%2;" : "=l"(d) : "l"(a), "l"(b)); return d;
}
static __device__ __forceinline__ u64 f2add(u64 a, u64 b) {
    u64 d; asm("add.rn.f32x2 %0,%1,%2;" : "=l"(d) : "l"(a), "l"(b)); return d;
}

// TWO rows per warp: lanes 0-15 -> row 2w, lanes 16-31 -> row 2w+1.
// Each lane owns 16 consecutive k (8 packed pairs), k0 = 16*(lane&15).
// k (and signs) pre-multiplied into z registers (f32x2: no spills at cap 51).
// Packed sin/cos pairs advance via the Chebyshev three-term recurrence
// w_{m+1} = (+-2cos2P)*w_m + w_{m-1}, eps=(+,+,-,-) folded into constants.
// T = tanh(u) tracked directly via the addition formula; the Moebius
// denominator 1/(1 - T*p) (|T*p| <= 0.1) is a 4-term Horner series
// (error <= 1.1e-5/step) - no MUFU.RCP on the state-update path.
__global__ void __launch_bounds__(128, 10) refiner_kernel(
    const float* __restrict__ z_real,
    const float* __restrict__ z_imag,
    const float* __restrict__ theta0_deg,
    const float* __restrict__ r0_m,
    const float* __restrict__ a_th_raw,
    const float* __restrict__ a_r_raw,
    const float* __restrict__ l_th_raw,
    const float* __restrict__ l_r_raw,
    float* __restrict__ out,
    int B)
{
    __shared__ float4 s_par[10];   // (a_th, a_r, l_th, l_r) per step
    int tid = threadIdx.x;
    if (tid < 10) {
        float4 p;
        p.x = clampf(log1pf(expf(a_th_raw[tid])), 1e-6f, 0.2f);
        p.y = clampf(log1pf(expf(a_r_raw[tid])),  1e-6f, 0.2f);
        p.z = clampf(log1pf(expf(l_th_raw[tid])), 1e-6f, 1.0f);
        p.w = clampf(log1pf(expf(l_r_raw[tid])),  1e-6f, 1.0f);
        s_par[tid] = p;
    }
    __syncthreads();

    int gwarp = (int)((blockIdx.x * blockDim.x + tid) >> 5);
    int lane  = tid & 31;
    int half  = lane >> 4;
    int hl    = lane & 15;
    int row   = gwarp * 2 + half;
    if (row >= B) return;

    const float k0f = (float)(hl * 16);

    // Load 16 z values per array; fold eps*k (and the zim minus) in.
    const float4* zr4 = reinterpret_cast<const float4*>(z_real + (size_t)row * 256) + hl * 4;
    const float4* zi4 = reinterpret_cast<const float4*>(z_imag + (size_t)row * 256) + hl * 4;
    u64 kzre[8], knzim[8];
    {
        float zr[16], zi[16];
        #pragma unroll
        for (int q4 = 0; q4 < 4; q4++) {
            float4 a = zr4[q4], b = zi4[q4];
            zr[q4*4+0]=a.x; zr[q4*4+1]=a.y; zr[q4*4+2]=a.z; zr[q4*4+3]=a.w;
            zi[q4*4+0]=b.x; zi[q4*4+1]=b.y; zi[q4*4+2]=b.z; zi[q4*4+3]=b.w;
        }
        #pragma unroll
        for (int j = 0; j < 8; j++) {
            float eps = ((j >> 1) & 1) ? -1.0f : 1.0f;   // +,+,-,-,+,+,-,-
            float ka = eps * (k0f + (float)(2*j));
            float kb = eps * (k0f + (float)(2*j) + 1.0f);
            kzre[j]  = pk2(ka * zr[2*j],  kb * zr[2*j+1]);
            knzim[j] = pk2(-ka * zi[2*j], -kb * zi[2*j+1]);
        }
    }

    const float EPS = 1e-6f;
    // direct tanh-space init: T = tanh(atanh(y)) = y (clipped)
    float T0 = clampf(theta0_deg[row] * (1.0f / 60.0f), -1.0f + EPS, 1.0f - EPS);
    float T1 = fmaf(2.0f, clampf(r0_m[row] * (1.0f / 2000.0f), EPS, 1.0f - EPS), -1.0f);

    const float C_GTH = (PI_F * PI_F / 3.0f) / 16.0f;
    const float C_GR  = -(0.4f * PI_F) / 16.0f;

    #pragma unroll 1
    for (int t = 0; t < 10; t++) {
        float4 par = s_par[t];   // a_th, a_r, l_th, l_r

        float th_rad = T0 * (60.0f * PI_F / 180.0f);
        float sth, cth;
        __sincosf(th_rad, &sth, &cth);
        float q = fmaf(-0.2f, T1 + 1.0f, 0.5f * sth);

        float Pr = TWOPI * (q - rintf(q));
        float sP, cP;
        __sincosf(Pr, &sP, &cP);
        float twocP  = cP + cP;
        float twoc2P = fmaf(twocP, twocP, -2.0f);     // 2*cos(2P)
        u64 aP = pk2(twoc2P, twoc2P);
        u64 aN = pk2(-twoc2P, -twoc2P);

        // step coefficients computed BEFORE v (off the critical path)
        float sech0 = fmaf(-T0, T0, 1.0f);
        float sech1 = fmaf(-T1, T1, 1.0f);
        float cg_th = C_GTH * cth * sech0;
        float cg_r  = C_GR * sech1;
        float acg_th = par.x * cg_th;
        float acg_r  = par.y * cg_r;

        // starting pairs: w0 = (s(a0), s(a0+P)), w1 = (s(a0+2P), s(a0+3P))
        float f = k0f * q;
        float a0 = TWOPI * (f - rintf(f));
        float s0_, c0_;
        __sincosf(a0, &s0_, &c0_);
        float s1_ = fmaf(s0_, cP, c0_ * sP);
        float c1_ = fmaf(c0_, cP, -(s0_ * sP));
        float s2_ = fmaf(twocP, s1_, -s0_);
        float c2_ = fmaf(twocP, c1_, -c0_);
        float s3_ = fmaf(twocP, s2_, -s1_);
        float c3_ = fmaf(twocP, c2_, -c1_);

        u64 psS = pk2(s0_, s1_), psC = pk2(c0_, c1_);   // w_0
        u64 cuS = pk2(s2_, s3_), cuC = pk2(c2_, c3_);   // w_1

        // m = 0, 1 (init accumulators with mul: no zero-pack)
        u64 accS = f2mul(kzre[0], psS);
        u64 accC = f2mul(knzim[0], psC);
        accS = f2fma(kzre[1], cuS, accS);
        accC = f2fma(knzim[1], cuC, accC);
        // m = 2..7: advance Chebyshev (alpha alternates -,+,-,+,-,+), accumulate
        #pragma unroll
        for (int m = 2; m < 8; m++) {
            u64 alpha = (m & 1) ? aP : aN;
            u64 nS = f2fma(alpha, cuS, psS);
            u64 nC = f2fma(alpha, cuC, psC);
            psS = cuS; cuS = nS;
            psC = cuC; cuC = nC;
            accS = f2fma(kzre[m], cuS, accS);
            accC = f2fma(knzim[m], cuC, accC);
        }

        u64 v2 = f2add(accS, accC);
        float vlo, vhi;
        upk2(v2, vlo, vhi);
        float v = vlo + vhi;
        #pragma unroll
        for (int o = 8; o > 0; o >>= 1)
            v += __shfl_xor_sync(0xffffffffu, v, o);

        float g_th = cg_th * v;
        float g_r  = cg_r * v;
        float den_th = fmaxf(fabsf(g_th), 1e-6f) + par.z;
        float den_r  = fmaxf(fabsf(g_r),  1e-6f) + par.w;
        float st_th = clampf(acg_th * v * __fdividef(1.0f, den_th), -0.1f, 0.1f);
        float st_r  = clampf(acg_r  * v * __fdividef(1.0f, den_r),  -0.1f, 0.1f);

        // T <- tanh(u - st); p = tanh(st) ~ st(1 - st^2/3).
        // 1/(1 - T*p) via 4-term Horner (|T*p| <= 0.1, err <= 1.1e-5): no RCP.
        float p_th = st_th * fmaf(st_th * st_th, -(1.0f / 3.0f), 1.0f);
        float p_r  = st_r  * fmaf(st_r  * st_r,  -(1.0f / 3.0f), 1.0f);
        float x0 = T0 * p_th;
        float x1 = T1 * p_r;
        float inv0 = fmaf(x0, fmaf(x0, fmaf(x0, fmaf(x0, 1.0f, 1.0f), 1.0f), 1.0f), 1.0f);
        float inv1 = fmaf(x1, fmaf(x1, fmaf(x1, fmaf(x1, 1.0f, 1.0f), 1.0f), 1.0f), 1.0f);
        T0 = (T0 - p_th) * inv0;
        T1 = (T1 - p_r)  * inv1;
    }

    if (hl == 0) {
        float2 o;
        o.x = 60.0f * T0;
        o.y = 1000.0f * (T1 + 1.0f);
        reinterpret_cast<float2*>(out)[row] = o;
    }
}

extern "C" void kernel_launch(void* const* d_in, const int* in_sizes, int n_in,
                              void* d_out, int out_size) {
    const float* z_real    = (const float*)d_in[0];
    const float* z_imag    = (const float*)d_in[1];
    const float* theta0    = (const float*)d_in[2];
    const float* r0        = (const float*)d_in[3];
    const float* a_th_raw  = (const float*)d_in[4];
    const float* a_r_raw   = (const float*)d_in[5];
    const float* l_th_raw  = (const float*)d_in[6];
    const float* l_r_raw   = (const float*)d_in[7];
    float* out = (float*)d_out;

    int B = in_sizes[2];
    int nwarps = (B + 1) / 2;
    int threads = 128;
    int blocks = (nwarps * 32 + threads - 1) / threads;
    refiner_kernel<<<blocks, threads>>>(z_real, z_imag, theta0, r0,
                                        a_th_raw, a_r_raw, l_th_raw, l_r_raw,
                                        out, B);
}